// round 10
// baseline (speedup 1.0000x reference)
#include <cuda_runtime.h>

#define DIM    256    // DIM_IN
#define BATCH  1024   // B
#define NI     32640  // C(256,2)

#define TT     32     // i/j tile size (8 tiles of 32)
#define ROWS   128    // batch rows per block
#define NPAIR  36     // unordered tile pairs
#define NYB    (BATCH / ROWS)   // 8 y-blocks
#define PR     129    // transposed x-tile pitch over rows (odd -> conflict-free)

__constant__ unsigned char cTI[NPAIR] = {0,0,0,0,0,0,0,0, 1,1,1,1,1,1,1, 2,2,2,2,2,2,
                                         3,3,3,3,3, 4,4,4,4, 5,5,5, 6,6, 7};
__constant__ unsigned char cTJ[NPAIR] = {0,1,2,3,4,5,6,7, 1,2,3,4,5,6,7, 2,3,4,5,6,7,
                                         3,4,5,6,7, 4,5,6,7, 5,6,7, 6,7, 7};

// Per-pair partial sums (fully rewritten every run -> no init needed) + arrival counters.
__device__ float g_scratch[NPAIR * BATCH];   // 144KB
__device__ int   g_cnt[NYB];                 // zero at load; reset by last block each run

// Packed f32x2 FMA
__device__ __forceinline__ float2 fma2(float2 a, float2 b, float2 c) {
    float2 d;
    asm("fma.rn.f32x2 %0, %1, %2, %3;"
        : "=l"(*reinterpret_cast<unsigned long long*>(&d))
        : "l"(*reinterpret_cast<const unsigned long long*>(&a)),
          "l"(*reinterpret_cast<const unsigned long long*>(&b)),
          "l"(*reinterpret_cast<const unsigned long long*>(&c)));
    return d;
}

// out[b] = sum_{i<j} (w0+w1)*w0*w1 * x[b,i]*x[b,j]
// Block = one unordered tile pair x 128 rows. Warp = 32 rows (lanes) x 16 j:
// As loads are warp-BROADCAST (1 crossbar phase), x load is one conflict-free
// 128B phase -> 5 phases per 8 FFMA2 (was 6 per 4). Output via scratch +
// decoupled last-block reduction: no zero-init, no atomic adds, no spinning.
__global__ void __launch_bounds__(256, 2)
quad_kernel(const float* __restrict__ x, const float* __restrict__ w,
            float* __restrict__ out) {
    __shared__ __align__(16) float As[TT * TT];        // 4KB
    __shared__ __align__(16) float xIsT[TT * PR];      // [col i][row r], 16.5KB
    __shared__ __align__(16) float xJsT[TT * PR];      // [col j][row r], 16.5KB
    __shared__ float red[8][32];
    __shared__ int   sIsLast;

    const int t     = threadIdx.x;
    const int pair  = blockIdx.x;
    const int yb    = blockIdx.y;
    const int ibase = cTI[pair] * TT;
    const int jbase = cTJ[pair] * TT;
    const int rbase = yb * ROWS;

    // ---- A tile loads first (batched, coalesced: gi<gj -> consecutive k).
    float w0v[4], w1v[4];
    bool  val[4];
#pragma unroll
    for (int s = 0; s < 4; ++s) {
        const int idx = s * 256 + t;
        const int gi = ibase + (idx >> 5);
        const int gj = jbase + (idx & 31);
        val[s] = (gj > gi);
        const int k = val[s] ? (gi * 255 - (gi * (gi - 1)) / 2 + (gj - gi - 1)) : 0;
        w0v[s] = __ldg(&w[k]);
        w1v[s] = __ldg(&w[NI + k]);
    }

    // ---- x tiles: coalesced LDG (lane=col), transposed STS (stride PR odd -> CF).
#pragma unroll
    for (int half = 0; half < 2; ++half) {
        float rI[8], rJ[8];
#pragma unroll
        for (int s = 0; s < 8; ++s) {
            const int idx = (half * 8 + s) * 256 + t;
            const int row = idx >> 5, col = idx & 31;
            const float* xp = x + (long)(rbase + row) * DIM;
            rI[s] = __ldg(xp + ibase + col);
            rJ[s] = __ldg(xp + jbase + col);
        }
#pragma unroll
        for (int s = 0; s < 8; ++s) {
            const int idx = (half * 8 + s) * 256 + t;
            const int row = idx >> 5, col = idx & 31;
            xIsT[col * PR + row] = rI[s];
            xJsT[col * PR + row] = rJ[s];
        }
    }
    // As compute + store (overlaps with x-store tail)
#pragma unroll
    for (int s = 0; s < 4; ++s) {
        const int idx = s * 256 + t;
        As[idx] = val[s] ? (w0v[s] + w1v[s]) * w0v[s] * w1v[s] : 0.0f;
    }
    __syncthreads();

    // ---- Mainloop: warp w -> rowgroup g=w>>1, jgroup q=w&1 (16 j per warp).
    const int lane = t & 31, wp = t >> 5;
    const int g = wp >> 1, q = wp & 1;
    const int row = g * 32 + lane;
    const int j0  = q * 16;

    float2 acc[8];
#pragma unroll
    for (int jj = 0; jj < 8; ++jj) acc[jj] = make_float2(0.f, 0.f);

#pragma unroll
    for (int i = 0; i < TT; ++i) {
        const float xv = xIsT[i * PR + row];                    // 1 phase (CF)
        const float4 a0 = *reinterpret_cast<const float4*>(&As[i * TT + j0]);      // broadcast
        const float4 a1 = *reinterpret_cast<const float4*>(&As[i * TT + j0 + 4]);  // broadcast
        const float4 a2 = *reinterpret_cast<const float4*>(&As[i * TT + j0 + 8]);  // broadcast
        const float4 a3 = *reinterpret_cast<const float4*>(&As[i * TT + j0 + 12]); // broadcast
        const float2 xd = make_float2(xv, xv);
        acc[0] = fma2(xd, make_float2(a0.x, a0.y), acc[0]);
        acc[1] = fma2(xd, make_float2(a0.z, a0.w), acc[1]);
        acc[2] = fma2(xd, make_float2(a1.x, a1.y), acc[2]);
        acc[3] = fma2(xd, make_float2(a1.z, a1.w), acc[3]);
        acc[4] = fma2(xd, make_float2(a2.x, a2.y), acc[4]);
        acc[5] = fma2(xd, make_float2(a2.z, a2.w), acc[5]);
        acc[6] = fma2(xd, make_float2(a3.x, a3.y), acc[6]);
        acc[7] = fma2(xd, make_float2(a3.z, a3.w), acc[7]);
    }

    // ---- Epilogue: dot with x_J for this row (scalar CF LDS), pair-wise.
    float s = 0.0f;
#pragma unroll
    for (int jj = 0; jj < 8; ++jj) {
        s += acc[jj].x * xJsT[(j0 + 2 * jj)     * PR + row];
        s += acc[jj].y * xJsT[(j0 + 2 * jj + 1) * PR + row];
    }
    red[wp][lane] = s;
    __syncthreads();
    if (q == 0)   // combine the two j-halves; write this pair's row partial
        g_scratch[pair * BATCH + rbase + row] = red[wp][lane] + red[wp + 1][lane];

    // ---- Decoupled completion: 36th block per y-slice reduces scratch -> out.
    __threadfence();
    __syncthreads();
    if (t == 0) sIsLast = (atomicAdd(&g_cnt[yb], 1) == NPAIR - 1);
    __syncthreads();
    if (sIsLast) {
        if (t < ROWS) {
            float tot = 0.0f;
#pragma unroll
            for (int p = 0; p < NPAIR; ++p)
                tot += g_scratch[p * BATCH + rbase + t];
            out[rbase + t] = tot;
        }
        __syncthreads();
        if (t == 0) atomicExch(&g_cnt[yb], 0);   // replay-safe reset
    }
}

extern "C" void kernel_launch(void* const* d_in, const int* in_sizes, int n_in,
                              void* d_out, int out_size) {
    const float* x = (const float*)d_in[0];
    const float* w = (const float*)d_in[1];
    float* out = (float*)d_out;

    quad_kernel<<<dim3(NPAIR, NYB), 256>>>(x, w, out);   // ONE launch, 288 blocks
}